// round 1
// baseline (speedup 1.0000x reference)
#include <cuda_runtime.h>

#define A_N 100000
#define B_N 200000
#define NBN 6
#define FA 133
#define FB 147
#define H 256
#define M_N 5000
#define DEPTH 4

// ---------------- device scratch (no allocations allowed) ----------------
__device__ float g_input_atom[(size_t)A_N * H];
__device__ float g_input_bond[(size_t)B_N * H];
__device__ float g_message_atom[(size_t)A_N * H];
__device__ float g_message_bond[(size_t)B_N * H];
__device__ float g_tmp_bond[(size_t)B_N * H];
__device__ float g_agg[(size_t)A_N * H];
__device__ float g_h1[(size_t)A_N * H];
__device__ float g_ah[(size_t)A_N * H];
__device__ int   g_offsets[M_N];

static inline int cdiv(int a, int b) { return (a + b - 1) / b; }

// ---------------- generic fp32 GEMM: C[M,256] = A[M,K] @ B[K,256] ----------------
// BM=64, BN=256 (full N), BK=8, 256 threads, 8x8 microtile per thread.
constexpr int GBM = 64;
constexpr int GBN = 256;
constexpr int GBK = 8;

template<bool ACC, bool RELU, bool ADD, bool BIAS>
__global__ __launch_bounds__(256)
void gemm256(const float* __restrict__ Ap, const float* __restrict__ Bp,
             float* __restrict__ Cp, const float* __restrict__ addp,
             const float* __restrict__ biasp, int M, int K)
{
    __shared__ float As[GBK][GBM];
    __shared__ float Bs[GBK][GBN];
    const int tid = threadIdx.x;
    const int ty = tid >> 5;   // 0..7  (rows)
    const int tx = tid & 31;   // 0..31 (cols)
    const int m0 = blockIdx.x * GBM;

    float acc[8][8];
#pragma unroll
    for (int i = 0; i < 8; i++)
#pragma unroll
        for (int j = 0; j < 8; j++) acc[i][j] = 0.f;

    const int nk = (K + GBK - 1) / GBK;
    for (int kt = 0; kt < nk; kt++) {
        const int k0 = kt * GBK;
        // A tile: 64x8 = 512 elems, 2 per thread (coalesced 32B rows)
#pragma unroll
        for (int i = 0; i < 2; i++) {
            int e = tid + i * 256;
            int m = e >> 3, k = e & 7;
            int gr = m0 + m, gk = k0 + k;
            As[k][m] = (gr < M && gk < K) ? Ap[(long)gr * K + gk] : 0.f;
        }
        // B tile: 8x256 = 512 float4, 2 per thread
#pragma unroll
        for (int i = 0; i < 2; i++) {
            int e = tid + i * 256;
            int k = e >> 6;
            int c = (e & 63) << 2;
            int gk = k0 + k;
            float4 v = make_float4(0.f, 0.f, 0.f, 0.f);
            if (gk < K) v = *(const float4*)(Bp + (long)gk * GBN + c);
            *(float4*)(&Bs[k][c]) = v;
        }
        __syncthreads();
#pragma unroll
        for (int k = 0; k < GBK; k++) {
            float a[8], b[8];
            *(float4*)(a)     = *(const float4*)(&As[k][ty * 4]);
            *(float4*)(a + 4) = *(const float4*)(&As[k][32 + ty * 4]);
            *(float4*)(b)     = *(const float4*)(&Bs[k][tx * 4]);
            *(float4*)(b + 4) = *(const float4*)(&Bs[k][128 + tx * 4]);
#pragma unroll
            for (int i = 0; i < 8; i++)
#pragma unroll
                for (int j = 0; j < 8; j++)
                    acc[i][j] = fmaf(a[i], b[j], acc[i][j]);
        }
        __syncthreads();
    }

#pragma unroll
    for (int i = 0; i < 8; i++) {
        int r = m0 + ((i < 4) ? (ty * 4 + i) : (32 + ty * 4 + (i - 4)));
        if (r >= M) continue;
#pragma unroll
        for (int jh = 0; jh < 2; jh++) {
            int c = (jh == 0) ? (tx * 4) : (128 + tx * 4);
            long off = (long)r * GBN + c;
            float v[4];
#pragma unroll
            for (int q = 0; q < 4; q++) v[q] = acc[i][jh * 4 + q];
            if (ADD) {
                float4 t = *(const float4*)(addp + off);
                v[0] += t.x; v[1] += t.y; v[2] += t.z; v[3] += t.w;
            }
            if (BIAS) {
                float4 t = *(const float4*)(biasp + c);
                v[0] += t.x; v[1] += t.y; v[2] += t.z; v[3] += t.w;
            }
            if (ACC) {
                float4 t = *(const float4*)(Cp + off);
                v[0] += t.x; v[1] += t.y; v[2] += t.z; v[3] += t.w;
            }
            if (RELU) {
#pragma unroll
                for (int q = 0; q < 4; q++) v[q] = fmaxf(v[q], 0.f);
            }
            float4 o = make_float4(v[0], v[1], v[2], v[3]);
            *(float4*)(Cp + off) = o;
        }
    }
}

// ---------------- sum*max neighbor aggregation ----------------
// out[a,h] (+)= sum_j(mb[a2b[a,j],h]) * max_j(mb[a2b[a,j],h])
template<bool ACCUM>
__global__ __launch_bounds__(256)
void sum_max_kernel(const float* __restrict__ mb, const int* __restrict__ a2b,
                    float* __restrict__ outp)
{
    int a = blockIdx.x * 4 + (threadIdx.x >> 6);
    if (a >= A_N) return;
    int h = (threadIdx.x & 63) << 2;
    const int* ab = a2b + (long)a * NBN;
    float4 s = make_float4(0.f, 0.f, 0.f, 0.f);
    float4 mx = make_float4(-1e30f, -1e30f, -1e30f, -1e30f);
#pragma unroll
    for (int j = 0; j < NBN; j++) {
        float4 v = *(const float4*)(mb + (long)ab[j] * H + h);
        s.x += v.x; s.y += v.y; s.z += v.z; s.w += v.w;
        mx.x = fmaxf(mx.x, v.x); mx.y = fmaxf(mx.y, v.y);
        mx.z = fmaxf(mx.z, v.z); mx.w = fmaxf(mx.w, v.w);
    }
    long o = (long)a * H + h;
    float4 r = make_float4(s.x * mx.x, s.y * mx.y, s.z * mx.z, s.w * mx.w);
    if (ACCUM) {
        float4 c = *(const float4*)(outp + o);
        r.x += c.x; r.y += c.y; r.z += c.z; r.w += c.w;
    }
    *(float4*)(outp + o) = r;
}

// ---------------- bond message prep: tmp[b] = ma[b2a[b]] - mb[b2revb[b]] ----------------
__global__ __launch_bounds__(256)
void bond_pre_kernel(const float* __restrict__ ma, const float* __restrict__ mb,
                     const int* __restrict__ b2a, const int* __restrict__ b2revb,
                     float* __restrict__ tmp)
{
    int b = blockIdx.x * 4 + (threadIdx.x >> 6);
    if (b >= B_N) return;
    int h = (threadIdx.x & 63) << 2;
    int a = b2a[b];
    int rb = b2revb[b];
    float4 x = *(const float4*)(ma + (long)a * H + h);
    float4 y = *(const float4*)(mb + (long)rb * H + h);
    float4 r = make_float4(x.x - y.x, x.y - y.y, x.z - y.z, x.w - y.w);
    *(float4*)(tmp + (long)b * H + h) = r;
}

// ---------------- exclusive scan of molecule sizes (single block) ----------------
__global__ void scan_kernel(const int* __restrict__ sizes)
{
    __shared__ int part[1024];
    int t = threadIdx.x;
    const int CH = (M_N + 1023) / 1024;  // 5
    int base = t * CH;
    int s = 0;
    for (int i = 0; i < CH; i++) {
        int idx = base + i;
        if (idx < M_N) s += sizes[idx];
    }
    part[t] = s;
    __syncthreads();
    for (int off = 1; off < 1024; off <<= 1) {
        int v = (t >= off) ? part[t - off] : 0;
        __syncthreads();
        part[t] += v;
        __syncthreads();
    }
    int run = (t == 0) ? 0 : part[t - 1];
    for (int i = 0; i < CH; i++) {
        int idx = base + i;
        if (idx < M_N) { g_offsets[idx] = run; run += sizes[idx]; }
    }
}

// ---------------- per-molecule mean pooling ----------------
__global__ __launch_bounds__(64)
void pool_kernel(const float* __restrict__ ah, const int* __restrict__ sizes,
                 float* __restrict__ out)
{
    int m = blockIdx.x;
    int h = threadIdx.x << 2;
    int start = g_offsets[m];
    int n = sizes[m];
    float4 s = make_float4(0.f, 0.f, 0.f, 0.f);
    for (int i = 0; i < n; i++) {
        float4 v = *(const float4*)(ah + (long)(start + i) * H + h);
        s.x += v.x; s.y += v.y; s.z += v.z; s.w += v.w;
    }
    float inv = 1.0f / (float)n;
    float4 r = make_float4(s.x * inv, s.y * inv, s.z * inv, s.w * inv);
    *(float4*)(out + (long)m * H + h) = r;
}

// ---------------- launch ----------------
extern "C" void kernel_launch(void* const* d_in, const int* in_sizes, int n_in,
                              void* d_out, int out_size)
{
    const float* f_atoms = (const float*)d_in[0];
    const float* f_bonds = (const float*)d_in[1];
    const float* W_ia    = (const float*)d_in[2];
    const float* W_ib    = (const float*)d_in[3];
    const float* W_h     = (const float*)d_in[4];   // [DEPTH-1][H][H]
    const float* W_o     = (const float*)d_in[5];   // [H][H]
    const float* b_o     = (const float*)d_in[6];   // [H]
    const float* W_lr    = (const float*)d_in[7];   // [3H][H]
    const int*   a2b     = (const int*)d_in[8];
    const int*   b2a     = (const int*)d_in[9];
    const int*   b2revb  = (const int*)d_in[10];
    const int*   sizes   = (const int*)d_in[11];
    float* out = (float*)d_out;

    float *input_atom, *input_bond, *ma, *mb, *tmp, *agg, *h1, *ah;
    cudaGetSymbolAddress((void**)&input_atom, g_input_atom);
    cudaGetSymbolAddress((void**)&input_bond, g_input_bond);
    cudaGetSymbolAddress((void**)&ma, g_message_atom);
    cudaGetSymbolAddress((void**)&mb, g_message_bond);
    cudaGetSymbolAddress((void**)&tmp, g_tmp_bond);
    cudaGetSymbolAddress((void**)&agg, g_agg);
    cudaGetSymbolAddress((void**)&h1, g_h1);
    cudaGetSymbolAddress((void**)&ah, g_ah);

    // input projections (relu)
    gemm256<false, true, false, false><<<cdiv(A_N, GBM), 256>>>(f_atoms, W_ia, input_atom, nullptr, nullptr, A_N, FA);
    gemm256<false, true, false, false><<<cdiv(B_N, GBM), 256>>>(f_bonds, W_ib, input_bond, nullptr, nullptr, B_N, FB);

    cudaMemcpyAsync(ma, input_atom, sizeof(float) * (size_t)A_N * H, cudaMemcpyDeviceToDevice, 0);
    cudaMemcpyAsync(mb, input_bond, sizeof(float) * (size_t)B_N * H, cudaMemcpyDeviceToDevice, 0);

    // message passing
    for (int d = 0; d < DEPTH - 1; d++) {
        sum_max_kernel<true><<<cdiv(A_N, 4), 256>>>(mb, a2b, ma);            // ma += sum*max
        bond_pre_kernel<<<cdiv(B_N, 4), 256>>>(ma, mb, b2a, b2revb, tmp);    // tmp = ma[b2a]-mb[b2revb]
        gemm256<false, true, true, false><<<cdiv(B_N, GBM), 256>>>(
            tmp, W_h + (long)d * H * H, mb, input_bond, nullptr, B_N, H);    // mb = relu(input_bond + tmp@W_h[d])
    }

    // final aggregation + readout
    sum_max_kernel<false><<<cdiv(A_N, 4), 256>>>(mb, a2b, agg);

    // h1 = [agg, ma, input_atom] @ W_lr  (3 accumulating GEMMs over W_lr row slices)
    gemm256<false, false, false, false><<<cdiv(A_N, GBM), 256>>>(agg,        W_lr,             h1, nullptr, nullptr, A_N, H);
    gemm256<true,  false, false, false><<<cdiv(A_N, GBM), 256>>>(ma,         W_lr + H * H,     h1, nullptr, nullptr, A_N, H);
    gemm256<true,  false, false, false><<<cdiv(A_N, GBM), 256>>>(input_atom, W_lr + 2 * H * H, h1, nullptr, nullptr, A_N, H);

    // ah = relu(h1 @ W_o + b_o)
    gemm256<false, true, false, true><<<cdiv(A_N, GBM), 256>>>(h1, W_o, ah, nullptr, b_o, A_N, H);

    // ragged mean pool
    scan_kernel<<<1, 1024>>>(sizes);
    pool_kernel<<<M_N, 64>>>(ah, sizes, out);
}

// round 2
// speedup vs baseline: 1.1032x; 1.1032x over previous
#include <cuda_runtime.h>
#include <cstdint>

#define A_N 100000
#define B_N 200000
#define NBN 6
#define FA 133
#define FB 147
#define H 256
#define M_N 5000
#define DEPTH 4

// ---------------- device scratch (no allocations allowed) ----------------
__device__ float g_input_atom[(size_t)A_N * H];
__device__ float g_input_bond[(size_t)B_N * H];
__device__ float g_message_atom[(size_t)A_N * H];
__device__ float g_mb0[(size_t)B_N * H];
__device__ float g_mb1[(size_t)B_N * H];
__device__ float g_agg[(size_t)A_N * H];
__device__ float g_h1[(size_t)A_N * H];
__device__ float g_ah[(size_t)A_N * H];
__device__ int   g_offsets[M_N];

static inline int cdiv(int a, int b) { return (a + b - 1) / b; }

// =====================================================================
// Tensor-core GEMM (3xTF32 split for ~fp32 accuracy)
// C[M,256] = op(A)[M,K] @ B[K,256] with fused epilogues.
// BM=128, BN=128 (grid.y=2 covers N=256), BK=16, 256 threads.
// Warp layout: 2 (M) x 4 (N); warp tile 64x32; mma m16n8k8 tf32.
//
// MODE 0: plain A, scalar loads (any K), epilogue relu              (input proj)
// MODE 1: gathered A = ma[b2a[r]] - mbprev[b2revb[r]], K=256,
//         epilogue relu(addp + C)                                    (W_h loop)
// MODE 2: A from 3 sources (K=768), no epilogue                      (W_lr)
// MODE 3: plain A float4, K=256, epilogue relu(C + bias)             (W_o)
// =====================================================================
constexpr int BM = 128;
constexpr int BN = 128;
constexpr int BK = 16;
constexpr int PITCH = 132;

__device__ __forceinline__ void split_tf32(float x, float& hi, float& lo) {
    uint32_t h;
    asm("cvt.rna.tf32.f32 %0, %1;" : "=r"(h) : "f"(x));
    float hf = __uint_as_float(h);
    float r = x - hf;
    uint32_t l;
    asm("cvt.rna.tf32.f32 %0, %1;" : "=r"(l) : "f"(r));
    hi = hf;
    lo = __uint_as_float(l);
}

__device__ __forceinline__ void mma_tf32(float* c, const uint32_t* a, const uint32_t* b) {
    asm volatile(
        "mma.sync.aligned.m16n8k8.row.col.f32.tf32.tf32.f32 "
        "{%0,%1,%2,%3}, {%4,%5,%6,%7}, {%8,%9}, {%0,%1,%2,%3};\n"
        : "+f"(c[0]), "+f"(c[1]), "+f"(c[2]), "+f"(c[3])
        : "r"(a[0]), "r"(a[1]), "r"(a[2]), "r"(a[3]), "r"(b[0]), "r"(b[1]));
}

template<int MODE>
__global__ __launch_bounds__(256)
void gemm_tc(const float* __restrict__ Ap,   // MODE0/3: A; MODE1: ma; MODE2: src0
             const float* __restrict__ A2,   // MODE1: mb_prev; MODE2: src1
             const float* __restrict__ A3,   // MODE2: src2
             const int* __restrict__ gi1,    // MODE1: b2a
             const int* __restrict__ gi2,    // MODE1: b2revb
             const float* __restrict__ Bp,
             float* __restrict__ Cp,
             const float* __restrict__ addp,
             const float* __restrict__ biasp,
             int M, int K)
{
    __shared__ float As[2][BK][PITCH];
    __shared__ float Bs[2][BK][PITCH];
    __shared__ int sIdxA[BM];
    __shared__ int sIdxR[BM];

    const int tid = threadIdx.x;
    const int lane = tid & 31;
    const int wm = (tid >> 5) & 1;       // 0..1
    const int wn = tid >> 6;             // 0..3
    const int mbase = wm * 64;
    const int nbase = wn * 32;
    const int m0 = blockIdx.x * BM;
    const int n0 = blockIdx.y * BN;

    if (MODE == 1 && tid < BM) {
        int gm = min(m0 + tid, M - 1);
        sIdxA[tid] = gi1[gm];
        sIdxR[tid] = gi2[gm];
    }
    if (MODE == 1) __syncthreads();

    float acc[4][4][4];
#pragma unroll
    for (int mi = 0; mi < 4; mi++)
#pragma unroll
        for (int ni = 0; ni < 4; ni++)
#pragma unroll
            for (int q = 0; q < 4; q++) acc[mi][ni][q] = 0.f;

    const int nk = (K + BK - 1) / BK;

    float a_st[8];
    float4 b_st[2];

    // ---- stage loaders ----
    auto load_stage = [&](int kt) {
        if (MODE == 0) {
#pragma unroll
            for (int i = 0; i < 8; i++) {
                int e = i * 256 + tid;
                int m = e >> 4, k = e & 15;
                int gm = min(m0 + m, M - 1);
                int gk = kt * BK + k;
                a_st[i] = (gk < K) ? Ap[(long)gm * K + gk] : 0.f;
            }
        } else {
#pragma unroll
            for (int i = 0; i < 2; i++) {
                int e = i * 256 + tid;
                int m = e >> 2, q = e & 3;
                if (MODE == 1) {
                    int col = kt * BK + q * 4;
                    int ia = sIdxA[m], ir = sIdxR[m];
                    float4 va = *(const float4*)(Ap + ((long)ia << 8) + col);
                    float4 vr = *(const float4*)(A2 + ((long)ir << 8) + col);
                    float4 r = make_float4(va.x - vr.x, va.y - vr.y, va.z - vr.z, va.w - vr.w);
                    b_st[0] = b_st[0];  // no-op to appease unroller
                    a_st[i * 4 + 0] = r.x; a_st[i * 4 + 1] = r.y;
                    a_st[i * 4 + 2] = r.z; a_st[i * 4 + 3] = r.w;
                } else if (MODE == 2) {
                    int which = kt / 16;
                    const float* src = (which == 0) ? Ap : (which == 1) ? A2 : A3;
                    int gm = min(m0 + m, M - 1);
                    int col = (kt % 16) * BK + q * 4;
                    float4 r = *(const float4*)(src + ((long)gm << 8) + col);
                    a_st[i * 4 + 0] = r.x; a_st[i * 4 + 1] = r.y;
                    a_st[i * 4 + 2] = r.z; a_st[i * 4 + 3] = r.w;
                } else {  // MODE 3
                    int gm = min(m0 + m, M - 1);
                    int col = kt * BK + q * 4;
                    float4 r = *(const float4*)(Ap + ((long)gm << 8) + col);
                    a_st[i * 4 + 0] = r.x; a_st[i * 4 + 1] = r.y;
                    a_st[i * 4 + 2] = r.z; a_st[i * 4 + 3] = r.w;
                }
            }
        }
        // B tile: 16 x 128 floats = 512 float4, 2 per thread
#pragma unroll
        for (int i = 0; i < 2; i++) {
            int e = i * 256 + tid;
            int kb = e >> 5, q = e & 31;
            int gk = kt * BK + kb;
            float4 v = make_float4(0.f, 0.f, 0.f, 0.f);
            if (gk < K) v = *(const float4*)(Bp + (long)gk * 256 + n0 + q * 4);
            b_st[i] = v;
        }
    };

    auto store_stage = [&]() {
        if (MODE == 0) {
#pragma unroll
            for (int i = 0; i < 8; i++) {
                int e = i * 256 + tid;
                int m = e >> 4, k = e & 15;
                float hi, lo;
                split_tf32(a_st[i], hi, lo);
                As[0][k][m] = hi;
                As[1][k][m] = lo;
            }
        } else {
#pragma unroll
            for (int i = 0; i < 2; i++) {
                int e = i * 256 + tid;
                int m = e >> 2, q = e & 3;
#pragma unroll
                for (int j = 0; j < 4; j++) {
                    int k = q * 4 + j;
                    float hi, lo;
                    split_tf32(a_st[i * 4 + j], hi, lo);
                    As[0][k][m] = hi;
                    As[1][k][m] = lo;
                }
            }
        }
#pragma unroll
        for (int i = 0; i < 2; i++) {
            int e = i * 256 + tid;
            int kb = e >> 5, q = e & 31;
            float v[4] = {b_st[i].x, b_st[i].y, b_st[i].z, b_st[i].w};
#pragma unroll
            for (int j = 0; j < 4; j++) {
                float hi, lo;
                split_tf32(v[j], hi, lo);
                Bs[0][kb][q * 4 + j] = hi;
                Bs[1][kb][q * 4 + j] = lo;
            }
        }
    };

    load_stage(0);
    for (int kt = 0; kt < nk; kt++) {
        store_stage();
        __syncthreads();
        if (kt + 1 < nk) load_stage(kt + 1);

        const int ar = lane >> 2;
        const int aq = lane & 3;
#pragma unroll
        for (int ks = 0; ks < 2; ks++) {
            int kk = ks * 8 + aq;
            uint32_t bh[4][2], bl[4][2];
#pragma unroll
            for (int ni = 0; ni < 4; ni++) {
                int c = nbase + ni * 8 + ar;
                bh[ni][0] = __float_as_uint(Bs[0][kk][c]);
                bh[ni][1] = __float_as_uint(Bs[0][kk + 4][c]);
                bl[ni][0] = __float_as_uint(Bs[1][kk][c]);
                bl[ni][1] = __float_as_uint(Bs[1][kk + 4][c]);
            }
#pragma unroll
            for (int mi = 0; mi < 4; mi++) {
                int r = mbase + mi * 16 + ar;
                uint32_t ah[4], al[4];
                ah[0] = __float_as_uint(As[0][kk][r]);
                ah[1] = __float_as_uint(As[0][kk][r + 8]);
                ah[2] = __float_as_uint(As[0][kk + 4][r]);
                ah[3] = __float_as_uint(As[0][kk + 4][r + 8]);
                al[0] = __float_as_uint(As[1][kk][r]);
                al[1] = __float_as_uint(As[1][kk][r + 8]);
                al[2] = __float_as_uint(As[1][kk + 4][r]);
                al[3] = __float_as_uint(As[1][kk + 4][r + 8]);
#pragma unroll
                for (int ni = 0; ni < 4; ni++) {
                    mma_tf32(acc[mi][ni], ah, bh[ni]);
                    mma_tf32(acc[mi][ni], ah, bl[ni]);
                    mma_tf32(acc[mi][ni], al, bh[ni]);
                }
            }
        }
        __syncthreads();
    }

    // ---- epilogue ----
#pragma unroll
    for (int mi = 0; mi < 4; mi++) {
        int r0 = m0 + mbase + mi * 16 + (lane >> 2);
#pragma unroll
        for (int ni = 0; ni < 4; ni++) {
            int c = n0 + nbase + ni * 8 + (lane & 3) * 2;
#pragma unroll
            for (int half = 0; half < 2; half++) {
                int r = r0 + half * 8;
                if (r >= M) continue;
                float x = acc[mi][ni][half * 2 + 0];
                float y = acc[mi][ni][half * 2 + 1];
                long o = (long)r * 256 + c;
                if (MODE == 1) {
                    float2 t = *(const float2*)(addp + o);
                    x += t.x; y += t.y;
                }
                if (MODE == 3) {
                    float2 t = *(const float2*)(biasp + c);
                    x += t.x; y += t.y;
                }
                if (MODE == 0 || MODE == 1 || MODE == 3) {
                    x = fmaxf(x, 0.f);
                    y = fmaxf(y, 0.f);
                }
                float2 o2 = make_float2(x, y);
                *(float2*)(Cp + o) = o2;
            }
        }
    }
}

// ---------------- sum*max neighbor aggregation ----------------
template<bool ADD>
__global__ __launch_bounds__(256)
void sum_max_kernel(const float* __restrict__ mb, const int* __restrict__ a2b,
                    const float* __restrict__ addsrc, float* __restrict__ outp)
{
    int a = blockIdx.x * 4 + (threadIdx.x >> 6);
    if (a >= A_N) return;
    int h = (threadIdx.x & 63) << 2;
    const int* ab = a2b + (long)a * NBN;
    float4 s = make_float4(0.f, 0.f, 0.f, 0.f);
    float4 mx = make_float4(-1e30f, -1e30f, -1e30f, -1e30f);
#pragma unroll
    for (int j = 0; j < NBN; j++) {
        float4 v = *(const float4*)(mb + (long)ab[j] * H + h);
        s.x += v.x; s.y += v.y; s.z += v.z; s.w += v.w;
        mx.x = fmaxf(mx.x, v.x); mx.y = fmaxf(mx.y, v.y);
        mx.z = fmaxf(mx.z, v.z); mx.w = fmaxf(mx.w, v.w);
    }
    long o = (long)a * H + h;
    float4 r = make_float4(s.x * mx.x, s.y * mx.y, s.z * mx.z, s.w * mx.w);
    if (ADD) {
        float4 c = *(const float4*)(addsrc + o);
        r.x += c.x; r.y += c.y; r.z += c.z; r.w += c.w;
    }
    *(float4*)(outp + o) = r;
}

// ---------------- exclusive scan of molecule sizes (single block) ----------------
__global__ void scan_kernel(const int* __restrict__ sizes)
{
    __shared__ int part[1024];
    int t = threadIdx.x;
    const int CH = (M_N + 1023) / 1024;  // 5
    int base = t * CH;
    int s = 0;
    for (int i = 0; i < CH; i++) {
        int idx = base + i;
        if (idx < M_N) s += sizes[idx];
    }
    part[t] = s;
    __syncthreads();
    for (int off = 1; off < 1024; off <<= 1) {
        int v = (t >= off) ? part[t - off] : 0;
        __syncthreads();
        part[t] += v;
        __syncthreads();
    }
    int run = (t == 0) ? 0 : part[t - 1];
    for (int i = 0; i < CH; i++) {
        int idx = base + i;
        if (idx < M_N) { g_offsets[idx] = run; run += sizes[idx]; }
    }
}

// ---------------- per-molecule mean pooling ----------------
__global__ __launch_bounds__(64)
void pool_kernel(const float* __restrict__ ah, const int* __restrict__ sizes,
                 float* __restrict__ out)
{
    int m = blockIdx.x;
    int h = threadIdx.x << 2;
    int start = g_offsets[m];
    int n = sizes[m];
    float4 s = make_float4(0.f, 0.f, 0.f, 0.f);
    for (int i = 0; i < n; i++) {
        float4 v = *(const float4*)(ah + (long)(start + i) * H + h);
        s.x += v.x; s.y += v.y; s.z += v.z; s.w += v.w;
    }
    float inv = 1.0f / (float)n;
    float4 r = make_float4(s.x * inv, s.y * inv, s.z * inv, s.w * inv);
    *(float4*)(out + (long)m * H + h) = r;
}

// ---------------- launch ----------------
extern "C" void kernel_launch(void* const* d_in, const int* in_sizes, int n_in,
                              void* d_out, int out_size)
{
    const float* f_atoms = (const float*)d_in[0];
    const float* f_bonds = (const float*)d_in[1];
    const float* W_ia    = (const float*)d_in[2];
    const float* W_ib    = (const float*)d_in[3];
    const float* W_h     = (const float*)d_in[4];   // [DEPTH-1][H][H]
    const float* W_o     = (const float*)d_in[5];   // [H][H]
    const float* b_o     = (const float*)d_in[6];   // [H]
    const float* W_lr    = (const float*)d_in[7];   // [3H][H]
    const int*   a2b     = (const int*)d_in[8];
    const int*   b2a     = (const int*)d_in[9];
    const int*   b2revb  = (const int*)d_in[10];
    const int*   sizes   = (const int*)d_in[11];
    float* out = (float*)d_out;

    float *input_atom, *input_bond, *ma, *mb0, *mb1, *agg, *h1, *ah;
    cudaGetSymbolAddress((void**)&input_atom, g_input_atom);
    cudaGetSymbolAddress((void**)&input_bond, g_input_bond);
    cudaGetSymbolAddress((void**)&ma, g_message_atom);
    cudaGetSymbolAddress((void**)&mb0, g_mb0);
    cudaGetSymbolAddress((void**)&mb1, g_mb1);
    cudaGetSymbolAddress((void**)&agg, g_agg);
    cudaGetSymbolAddress((void**)&h1, g_h1);
    cudaGetSymbolAddress((void**)&ah, g_ah);

    dim3 gA(cdiv(A_N, BM), 2), gB(cdiv(B_N, BM), 2);

    // input projections (relu)
    gemm_tc<0><<<gA, 256>>>(f_atoms, nullptr, nullptr, nullptr, nullptr,
                            W_ia, input_atom, nullptr, nullptr, A_N, FA);
    gemm_tc<0><<<gB, 256>>>(f_bonds, nullptr, nullptr, nullptr, nullptr,
                            W_ib, input_bond, nullptr, nullptr, B_N, FB);

    // message passing (ping-pong bond buffers; no copies)
    const float* mbcur = input_bond;
    for (int d = 0; d < DEPTH - 1; d++) {
        // ma = (d==0 ? input_atom : ma) + sum*max over current bond messages
        sum_max_kernel<true><<<cdiv(A_N, 4), 256>>>(mbcur, a2b,
                                                    (d == 0) ? input_atom : ma, ma);
        float* mbout = (d % 2 == 0) ? mb0 : mb1;
        // mbout = relu(input_bond + (ma[b2a] - mbcur[b2revb]) @ W_h[d])
        gemm_tc<1><<<gB, 256>>>(ma, mbcur, nullptr, b2a, b2revb,
                                W_h + (long)d * H * H, mbout, input_bond, nullptr,
                                B_N, H);
        mbcur = mbout;
    }

    // final aggregation (mbcur == mb0 after 3 iterations)
    sum_max_kernel<false><<<cdiv(A_N, 4), 256>>>(mbcur, a2b, nullptr, agg);

    // h1 = [agg, ma, input_atom] @ W_lr  (single K=768 GEMM with 3 A sources)
    gemm_tc<2><<<gA, 256>>>(agg, ma, input_atom, nullptr, nullptr,
                            W_lr, h1, nullptr, nullptr, A_N, 3 * H);

    // ah = relu(h1 @ W_o + b_o)
    gemm_tc<3><<<gA, 256>>>(h1, nullptr, nullptr, nullptr, nullptr,
                            W_o, ah, nullptr, b_o, A_N, H);

    // ragged mean pool
    scan_kernel<<<1, 1024>>>(sizes);
    pool_kernel<<<M_N, 64>>>(ah, sizes, out);
}

// round 4
// speedup vs baseline: 1.5138x; 1.3722x over previous
#include <cuda_runtime.h>
#include <cstdint>

#define A_N 100000
#define B_N 200000
#define NBN 6
#define FA 133
#define FB 147
#define H 256
#define M_N 5000
#define DEPTH 4

// ---------------- device scratch (no allocations allowed) ----------------
__device__ float g_input_atom[(size_t)A_N * H];
__device__ float g_input_bond[(size_t)B_N * H];
__device__ float g_message_atom[(size_t)A_N * H];
__device__ float g_mb0[(size_t)B_N * H];
__device__ float g_mb1[(size_t)B_N * H];
__device__ float g_agg[(size_t)A_N * H];
__device__ float g_h1[(size_t)A_N * H];
__device__ float g_ah[(size_t)A_N * H];
__device__ int   g_offsets[M_N];

// pre-formatted B weights: per region (ny, kb16) 4096 floats, fragment layout,
// element idx = ((nig*2+ks)*32 + lane)*4 + slot, slots = {bh0, bh1, bl0, bl1}
// region count = 2 * ceil(K/16) per weight
#define OFF_WIA 0         // 18 regions
#define OFF_WIB 73728     // 20
#define OFF_WH  155648    // 3 * 32
#define OFF_WLR 548864    // 96
#define OFF_WO  942080    // 32
#define FMT_TOTAL 1073152
__device__ float g_fmt[FMT_TOTAL];

static inline int cdiv(int a, int b) { return (a + b - 1) / b; }

// ================= helpers =================
__device__ __forceinline__ uint32_t smem_u32(const void* p) {
    uint32_t a;
    asm("{ .reg .u64 t; cvta.to.shared.u64 t, %1; cvt.u32.u64 %0, t; }" : "=r"(a) : "l"(p));
    return a;
}
__device__ __forceinline__ void split_tf32(float x, uint32_t& hi, uint32_t& lo) {
    uint32_t h;
    asm("cvt.rna.tf32.f32 %0, %1;" : "=r"(h) : "f"(x));
    float hf = __uint_as_float(h);
    float r = x - hf;
    uint32_t l;
    asm("cvt.rna.tf32.f32 %0, %1;" : "=r"(l) : "f"(r));
    hi = h; lo = l;
}
__device__ __forceinline__ void mma_tf32(float* c, const uint32_t* a, const uint32_t* b) {
    asm volatile(
        "mma.sync.aligned.m16n8k8.row.col.f32.tf32.tf32.f32 "
        "{%0,%1,%2,%3}, {%4,%5,%6,%7}, {%8,%9}, {%0,%1,%2,%3};\n"
        : "+f"(c[0]), "+f"(c[1]), "+f"(c[2]), "+f"(c[3])
        : "r"(a[0]), "r"(a[1]), "r"(a[2]), "r"(a[3]), "r"(b[0]), "r"(b[1]));
}
__device__ __forceinline__ void cp16(uint32_t dst, const void* src) {
    asm volatile("cp.async.cg.shared.global [%0], [%1], 16;" :: "r"(dst), "l"(src));
}

// ================= weight prep: split + fragment layout =================
// W is [K][256] row-major. region rb = ny*KB + kb; 128 threads, 32 elems each.
__global__ __launch_bounds__(128)
void prep_weight(const float* __restrict__ W, int K, int KB, long dstoff)
{
    const int rb = blockIdx.x;
    const int ny = rb / KB, kb = rb % KB;
    const int t = threadIdx.x;
    float* dst = g_fmt + dstoff + (long)rb * 4096;
#pragma unroll
    for (int i = 0; i < 32; i++) {
        int idx = i * 128 + t;
        int slot = idx & 3;
        int lane = (idx >> 2) & 31;
        int ks   = (idx >> 7) & 1;
        int nig  = idx >> 8;
        int nloc = nig * 8 + (lane >> 2);
        int kloc = ks * 8 + (slot & 1) * 4 + (lane & 3);
        int kg = kb * 16 + kloc;
        int ng = ny * 128 + nloc;
        float v = (kg < K) ? W[(long)kg * 256 + ng] : 0.f;
        uint32_t hi, lo;
        split_tf32(v, hi, lo);
        dst[idx] = __uint_as_float((slot >> 1) ? lo : hi);
    }
}

// ================= mma.sync tf32 3-split GEMM =================
// C[M,256] = op(A)[M,K] @ B[K,256]; CTA: 128 rows x 128 cols (grid.y = n-half)
// 256 threads = 8 warps (2 m x 4 n), warp tile 64x32, double-buffered k16 blocks.
// MODE 0: plain A scalar loads (ragged K), relu
// MODE 1: A = ma[b2a[r]] - mbprev[b2revb[r]] (K=256), relu(addp + C)
// MODE 2: A from 3 sources (K=768), plain store
// MODE 3: plain A (K=256), relu(C + bias)
template<int MODE>
__global__ __launch_bounds__(256)
void gemm_mma(const float* __restrict__ Ap, const float* __restrict__ A2,
              const float* __restrict__ A3,
              const int* __restrict__ gi1, const int* __restrict__ gi2,
              const float* __restrict__ fmt,
              float* __restrict__ Cp, const float* __restrict__ addp,
              const float* __restrict__ biasp, int M, int K, int KB)
{
    __shared__ float  As[2][2048];   // A fragment layout: ((mig*2+ks)*32+lane)*4+slot
    __shared__ float4 Bs[2][1024];   // B fragment layout: (nig*2+ks)*32+lane -> {bh0,bh1,bl0,bl1}

    const int tid = threadIdx.x;
    const int lane = tid & 31;
    const int wid = tid >> 5;
    const int wm = wid & 1;
    const int wn = wid >> 1;
    const int m0 = blockIdx.x * 128;
    const int n0 = blockIdx.y * 128;

    // staging identity: thread stages row srow, k-half skh (8 k each)
    const int srow = tid >> 1;
    const int skh = tid & 1;
    const int gm_s = min(m0 + srow, M - 1);
    int ia = 0, ir = 0;
    if (MODE == 1) { ia = gi1[gm_s]; ir = gi2[gm_s]; }

    // precomputed STS float-indices for the 8 staged elements
    int sts_idx[8];
    {
        int mig = srow >> 4;
#pragma unroll
        for (int j = 0; j < 8; j++) {
            int lt = ((srow & 7) << 2) | (j & 3);
            int slot = (((j >> 2) & 1) << 1) | ((srow >> 3) & 1);
            sts_idx[j] = ((mig * 2 + skh) * 32 + lt) * 4 + slot;
        }
    }

    float acc[4][4][4];
#pragma unroll
    for (int mi = 0; mi < 4; mi++)
#pragma unroll
        for (int ni = 0; ni < 4; ni++)
#pragma unroll
            for (int q = 0; q < 4; q++) acc[mi][ni][q] = 0.f;

    float areg[8];

    auto loadA = [&](int kb) {
        const int kbase = kb * 16 + skh * 8;
        if (MODE == 0) {
            const float* row = Ap + (long)gm_s * K + kbase;
#pragma unroll
            for (int j = 0; j < 8; j++) areg[j] = (kbase + j < K) ? row[j] : 0.f;
        } else if (MODE == 1) {
            const float* ra = Ap + ((long)ia << 8) + kbase;
            const float* rr = A2 + ((long)ir << 8) + kbase;
            float4 x0 = *(const float4*)ra, x1 = *(const float4*)(ra + 4);
            float4 y0 = *(const float4*)rr, y1 = *(const float4*)(rr + 4);
            areg[0] = x0.x - y0.x; areg[1] = x0.y - y0.y; areg[2] = x0.z - y0.z; areg[3] = x0.w - y0.w;
            areg[4] = x1.x - y1.x; areg[5] = x1.y - y1.y; areg[6] = x1.z - y1.z; areg[7] = x1.w - y1.w;
        } else if (MODE == 2) {
            int which = kb >> 4;
            const float* src = (which == 0) ? Ap : (which == 1) ? A2 : A3;
            const float* ra = src + ((long)gm_s << 8) + (kb & 15) * 16 + skh * 8;
            float4 x0 = *(const float4*)ra, x1 = *(const float4*)(ra + 4);
            areg[0] = x0.x; areg[1] = x0.y; areg[2] = x0.z; areg[3] = x0.w;
            areg[4] = x1.x; areg[5] = x1.y; areg[6] = x1.z; areg[7] = x1.w;
        } else {
            const float* ra = Ap + ((long)gm_s << 8) + kbase;
            float4 x0 = *(const float4*)ra, x1 = *(const float4*)(ra + 4);
            areg[0] = x0.x; areg[1] = x0.y; areg[2] = x0.z; areg[3] = x0.w;
            areg[4] = x1.x; areg[5] = x1.y; areg[6] = x1.z; areg[7] = x1.w;
        }
    };

    auto issueB = [&](int kb, int buf) {
        const float4* src = (const float4*)fmt + (long)(blockIdx.y * KB + kb) * 1024;
        uint32_t dst = smem_u32(&Bs[buf][0]);
#pragma unroll
        for (int i = 0; i < 4; i++) {
            int idx = i * 256 + tid;
            cp16(dst + idx * 16, src + idx);
        }
        asm volatile("cp.async.commit_group;" ::: "memory");
    };

    auto storeA = [&](int buf) {
#pragma unroll
        for (int j = 0; j < 8; j++) As[buf][sts_idx[j]] = areg[j];
    };

    auto compute = [&](int buf) {
        const float* a_s = As[buf];
        const float4* b_s = Bs[buf];
#pragma unroll
        for (int ks = 0; ks < 2; ks++) {
            uint32_t bh[4][2], bl[4][2];
#pragma unroll
            for (int ni = 0; ni < 4; ni++) {
                int nig = wn * 4 + ni;
                float4 f = b_s[(nig * 2 + ks) * 32 + lane];
                bh[ni][0] = __float_as_uint(f.x); bh[ni][1] = __float_as_uint(f.y);
                bl[ni][0] = __float_as_uint(f.z); bl[ni][1] = __float_as_uint(f.w);
            }
#pragma unroll
            for (int mi = 0; mi < 4; mi++) {
                int mig = wm * 4 + mi;
                float4 ra = *(const float4*)(a_s + ((mig * 2 + ks) * 32 + lane) * 4);
                uint32_t ah[4], al[4];
                split_tf32(ra.x, ah[0], al[0]);
                split_tf32(ra.y, ah[1], al[1]);
                split_tf32(ra.z, ah[2], al[2]);
                split_tf32(ra.w, ah[3], al[3]);
#pragma unroll
                for (int ni = 0; ni < 4; ni++) {
                    mma_tf32(acc[mi][ni], ah, bh[ni]);
                    mma_tf32(acc[mi][ni], ah, bl[ni]);
                    mma_tf32(acc[mi][ni], al, bh[ni]);
                }
            }
        }
    };

    // prologue
    loadA(0);
    issueB(0, 0);
    storeA(0);
    asm volatile("cp.async.wait_group 0;" ::: "memory");
    __syncthreads();

    for (int kb = 0; kb < KB; kb++) {
        const int buf = kb & 1;
        const bool more = (kb + 1 < KB);
        if (more) { loadA(kb + 1); issueB(kb + 1, buf ^ 1); }
        compute(buf);
        if (more) {
            storeA(buf ^ 1);
            asm volatile("cp.async.wait_group 0;" ::: "memory");
        }
        __syncthreads();
    }

    // epilogue
#pragma unroll
    for (int mi = 0; mi < 4; mi++) {
        int r0 = m0 + wm * 64 + mi * 16 + (lane >> 2);
#pragma unroll
        for (int ni = 0; ni < 4; ni++) {
            int c = n0 + wn * 32 + ni * 8 + (lane & 3) * 2;
#pragma unroll
            for (int half = 0; half < 2; half++) {
                int r = r0 + half * 8;
                if (r >= M) continue;
                float x = acc[mi][ni][half * 2 + 0];
                float y = acc[mi][ni][half * 2 + 1];
                long o = (long)r * 256 + c;
                if (MODE == 1) {
                    float2 t = *(const float2*)(addp + o);
                    x += t.x; y += t.y;
                }
                if (MODE == 3) {
                    float2 t = *(const float2*)(biasp + c);
                    x += t.x; y += t.y;
                }
                if (MODE != 2) { x = fmaxf(x, 0.f); y = fmaxf(y, 0.f); }
                *(float2*)(Cp + o) = make_float2(x, y);
            }
        }
    }
}

// ---------------- sum*max neighbor aggregation ----------------
template<bool ADD>
__global__ __launch_bounds__(256)
void sum_max_kernel(const float* __restrict__ mb, const int* __restrict__ a2b,
                    const float* __restrict__ addsrc, float* __restrict__ outp)
{
    int a = blockIdx.x * 4 + (threadIdx.x >> 6);
    if (a >= A_N) return;
    int h = (threadIdx.x & 63) << 2;
    const int* ab = a2b + (long)a * NBN;
    float4 s = make_float4(0.f, 0.f, 0.f, 0.f);
    float4 mx = make_float4(-1e30f, -1e30f, -1e30f, -1e30f);
#pragma unroll
    for (int j = 0; j < NBN; j++) {
        float4 v = *(const float4*)(mb + (long)ab[j] * H + h);
        s.x += v.x; s.y += v.y; s.z += v.z; s.w += v.w;
        mx.x = fmaxf(mx.x, v.x); mx.y = fmaxf(mx.y, v.y);
        mx.z = fmaxf(mx.z, v.z); mx.w = fmaxf(mx.w, v.w);
    }
    long o = (long)a * H + h;
    float4 r = make_float4(s.x * mx.x, s.y * mx.y, s.z * mx.z, s.w * mx.w);
    if (ADD) {
        float4 c = *(const float4*)(addsrc + o);
        r.x += c.x; r.y += c.y; r.z += c.z; r.w += c.w;
    }
    *(float4*)(outp + o) = r;
}

// ---------------- exclusive scan of molecule sizes ----------------
__global__ void scan_kernel(const int* __restrict__ sizes)
{
    __shared__ int part[1024];
    int t = threadIdx.x;
    const int CH = (M_N + 1023) / 1024;
    int base = t * CH;
    int s = 0;
    for (int i = 0; i < CH; i++) {
        int idx = base + i;
        if (idx < M_N) s += sizes[idx];
    }
    part[t] = s;
    __syncthreads();
    for (int off = 1; off < 1024; off <<= 1) {
        int v = (t >= off) ? part[t - off] : 0;
        __syncthreads();
        part[t] += v;
        __syncthreads();
    }
    int run = (t == 0) ? 0 : part[t - 1];
    for (int i = 0; i < CH; i++) {
        int idx = base + i;
        if (idx < M_N) { g_offsets[idx] = run; run += sizes[idx]; }
    }
}

// ---------------- per-molecule mean pooling ----------------
__global__ __launch_bounds__(64)
void pool_kernel(const float* __restrict__ ah, const int* __restrict__ sizes,
                 float* __restrict__ out)
{
    int m = blockIdx.x;
    int h = threadIdx.x << 2;
    int start = g_offsets[m];
    int n = sizes[m];
    float4 s = make_float4(0.f, 0.f, 0.f, 0.f);
    for (int i = 0; i < n; i++) {
        float4 v = *(const float4*)(ah + (long)(start + i) * H + h);
        s.x += v.x; s.y += v.y; s.z += v.z; s.w += v.w;
    }
    float inv = 1.0f / (float)n;
    *(float4*)(out + (long)m * H + h) = make_float4(s.x * inv, s.y * inv, s.z * inv, s.w * inv);
}

// ---------------- launch ----------------
extern "C" void kernel_launch(void* const* d_in, const int* in_sizes, int n_in,
                              void* d_out, int out_size)
{
    const float* f_atoms = (const float*)d_in[0];
    const float* f_bonds = (const float*)d_in[1];
    const float* W_ia    = (const float*)d_in[2];
    const float* W_ib    = (const float*)d_in[3];
    const float* W_h     = (const float*)d_in[4];
    const float* W_o     = (const float*)d_in[5];
    const float* b_o     = (const float*)d_in[6];
    const float* W_lr    = (const float*)d_in[7];
    const int*   a2b     = (const int*)d_in[8];
    const int*   b2a     = (const int*)d_in[9];
    const int*   b2revb  = (const int*)d_in[10];
    const int*   sizes   = (const int*)d_in[11];
    float* out = (float*)d_out;

    float *input_atom, *input_bond, *ma, *mb0, *mb1, *agg, *h1, *ah, *fmt;
    cudaGetSymbolAddress((void**)&input_atom, g_input_atom);
    cudaGetSymbolAddress((void**)&input_bond, g_input_bond);
    cudaGetSymbolAddress((void**)&ma, g_message_atom);
    cudaGetSymbolAddress((void**)&mb0, g_mb0);
    cudaGetSymbolAddress((void**)&mb1, g_mb1);
    cudaGetSymbolAddress((void**)&agg, g_agg);
    cudaGetSymbolAddress((void**)&h1, g_h1);
    cudaGetSymbolAddress((void**)&ah, g_ah);
    cudaGetSymbolAddress((void**)&fmt, g_fmt);

    // weight prep (tf32 split + fragment layout), KB = ceil(K/16)
    prep_weight<<<2 * 9, 128>>>(W_ia, FA, 9, OFF_WIA);
    prep_weight<<<2 * 10, 128>>>(W_ib, FB, 10, OFF_WIB);
    for (int d = 0; d < DEPTH - 1; d++)
        prep_weight<<<2 * 16, 128>>>(W_h + (long)d * H * H, H, 16, OFF_WH + (long)d * 131072);
    prep_weight<<<2 * 48, 128>>>(W_lr, 3 * H, 48, OFF_WLR);
    prep_weight<<<2 * 16, 128>>>(W_o, H, 16, OFF_WO);

    dim3 gA(cdiv(A_N, 128), 2), gB(cdiv(B_N, 128), 2);

    // input projections (relu)
    gemm_mma<0><<<gA, 256>>>(f_atoms, nullptr, nullptr, nullptr, nullptr,
                             fmt + OFF_WIA, input_atom, nullptr, nullptr, A_N, FA, 9);
    gemm_mma<0><<<gB, 256>>>(f_bonds, nullptr, nullptr, nullptr, nullptr,
                             fmt + OFF_WIB, input_bond, nullptr, nullptr, B_N, FB, 10);

    // message passing (ping-pong bond buffers)
    const float* mbcur = input_bond;
    for (int d = 0; d < DEPTH - 1; d++) {
        sum_max_kernel<true><<<cdiv(A_N, 4), 256>>>(mbcur, a2b,
                                                    (d == 0) ? input_atom : ma, ma);
        float* mbout = (d % 2 == 0) ? mb0 : mb1;
        gemm_mma<1><<<gB, 256>>>(ma, mbcur, nullptr, b2a, b2revb,
                                 fmt + OFF_WH + (long)d * 131072,
                                 mbout, input_bond, nullptr, B_N, H, 16);
        mbcur = mbout;
    }

    // final aggregation + readout
    sum_max_kernel<false><<<cdiv(A_N, 4), 256>>>(mbcur, a2b, nullptr, agg);

    gemm_mma<2><<<gA, 256>>>(agg, ma, input_atom, nullptr, nullptr,
                             fmt + OFF_WLR, h1, nullptr, nullptr, A_N, 3 * H, 48);

    gemm_mma<3><<<gA, 256>>>(h1, nullptr, nullptr, nullptr, nullptr,
                             fmt + OFF_WO, ah, nullptr, b_o, A_N, H, 16);

    scan_kernel<<<1, 1024>>>(sizes);
    pool_kernel<<<M_N, 64>>>(ah, sizes, out);
}